// round 12
// baseline (speedup 1.0000x reference)
#include <cuda_runtime.h>
#include <cuda_bf16.h>
#include <cstdint>

#define BB 4
#define SS 2048
#define DDIM 1024
#define HH 16
#define DH 64
#define MM (BB*SS)

// Head-major scratch [B,H,S,Dh] fp32 (allocation-free: __device__ globals)
__device__ float g_Qh[(size_t)BB*HH*SS*DH];
__device__ float g_Kh[(size_t)BB*HH*SS*DH];
__device__ float g_Vh[(size_t)BB*HH*SS*DH];

__device__ __forceinline__ uint32_t f2tf(float x){
    uint32_t y; asm("cvt.rna.tf32.f32 %0, %1;" : "=r"(y) : "f"(x)); return y;
}
__device__ __forceinline__ uint32_t f2tf_u(uint32_t x){
    return f2tf(__uint_as_float(x));
}
__device__ __forceinline__ float ex2f(float x){
    float y; asm("ex2.approx.ftz.f32 %0, %1;" : "=f"(y) : "f"(x)); return y;
}
__device__ __forceinline__ void mma8(float* d, const uint32_t* a, const uint32_t* b){
    asm volatile(
        "mma.sync.aligned.m16n8k8.row.col.f32.tf32.tf32.f32 "
        "{%0,%1,%2,%3},{%4,%5,%6,%7},{%8,%9},{%0,%1,%2,%3};\n"
        : "+f"(d[0]), "+f"(d[1]), "+f"(d[2]), "+f"(d[3])
        : "r"(a[0]), "r"(a[1]), "r"(a[2]), "r"(a[3]), "r"(b[0]), "r"(b[1]));
}
__device__ __forceinline__ void cpa16(uint32_t dst, const float* src){
    asm volatile("cp.async.ca.shared.global [%0], [%1], 16;" :: "r"(dst), "l"(src));
}
#define CP_COMMIT() asm volatile("cp.async.commit_group;" ::: "memory")
#define CP_WAIT0()  asm volatile("cp.async.wait_group 0;" ::: "memory")

// ============================================================================
// Projection v3 (unchanged from R10/R11 pass): CTA tile 128x128, BK=16,
// 8 warps, double-buffered k-loop with register prefetch, one barrier/iter.
// ============================================================================
__global__ __launch_bounds__(256, 2) void proj_kernel(const float* __restrict__ Xq,
                                                      const float* __restrict__ Xk,
                                                      const float* __restrict__ Xv,
                                                      const float* __restrict__ Wq,
                                                      const float* __restrict__ Wk,
                                                      const float* __restrict__ Wv){
    __shared__ uint32_t Xs[2][128][20];
    __shared__ uint32_t Ws[2][128][20];

    const int which = blockIdx.z;
    const float* X = (which == 0) ? Xq : (which == 1) ? Xk : Xv;
    const float* W = (which == 0) ? Wq : (which == 1) ? Wk : Wv;
    float* Out     = (which == 0) ? g_Qh : (which == 1) ? g_Kh : g_Vh;

    const int tid  = threadIdx.x;
    const int wid  = tid >> 5, lane = tid & 31;
    const int g    = lane >> 2, tig = lane & 3;
    const int wm   = wid & 3,  wn  = wid >> 2;
    const int m0   = blockIdx.y * 128;
    const int n0   = blockIdx.x * 128;

    int srow[2], sc4[2];
    #pragma unroll
    for (int i=0;i<2;i++){
        int idx = tid + i*256;
        srow[i] = idx >> 2;
        sc4[i]  = idx & 3;
    }
    const float* Xrow0 = X + (size_t)(m0+srow[0])*DDIM + sc4[0]*4;
    const float* Xrow1 = X + (size_t)(m0+srow[1])*DDIM + sc4[1]*4;
    const float* Wrow0 = W + (size_t)(n0+srow[0])*DDIM + sc4[0]*4;
    const float* Wrow1 = W + (size_t)(n0+srow[1])*DDIM + sc4[1]*4;

    float acc[2][8][4];
    #pragma unroll
    for (int i=0;i<2;i++)
        #pragma unroll
        for (int j=0;j<8;j++)
            #pragma unroll
            for (int c=0;c<4;c++) acc[i][j][c]=0.f;

    float4 xr0 = *(const float4*)(Xrow0);
    float4 xr1 = *(const float4*)(Xrow1);
    float4 wr0 = *(const float4*)(Wrow0);
    float4 wr1 = *(const float4*)(Wrow1);
    *(uint4*)&Xs[0][srow[0]][sc4[0]*4] = make_uint4(f2tf(xr0.x),f2tf(xr0.y),f2tf(xr0.z),f2tf(xr0.w));
    *(uint4*)&Xs[0][srow[1]][sc4[1]*4] = make_uint4(f2tf(xr1.x),f2tf(xr1.y),f2tf(xr1.z),f2tf(xr1.w));
    *(uint4*)&Ws[0][srow[0]][sc4[0]*4] = make_uint4(f2tf(wr0.x),f2tf(wr0.y),f2tf(wr0.z),f2tf(wr0.w));
    *(uint4*)&Ws[0][srow[1]][sc4[1]*4] = make_uint4(f2tf(wr1.x),f2tf(wr1.y),f2tf(wr1.z),f2tf(wr1.w));
    __syncthreads();

    for (int t = 0; t < 64; t++){
        const int cur = t & 1;
        if (t + 1 < 64){
            const int kt = (t + 1) * 16;
            xr0 = *(const float4*)(Xrow0 + kt);
            xr1 = *(const float4*)(Xrow1 + kt);
            wr0 = *(const float4*)(Wrow0 + kt);
            wr1 = *(const float4*)(Wrow1 + kt);
        }

        #pragma unroll
        for (int ks=0; ks<2; ks++){
            const int kb = ks*8;
            uint32_t a[2][4], b[8][2];
            #pragma unroll
            for (int mt=0; mt<2; mt++){
                int r = wm*32 + mt*16;
                a[mt][0]=Xs[cur][r+g  ][kb+tig  ];
                a[mt][1]=Xs[cur][r+g+8][kb+tig  ];
                a[mt][2]=Xs[cur][r+g  ][kb+tig+4];
                a[mt][3]=Xs[cur][r+g+8][kb+tig+4];
            }
            #pragma unroll
            for (int nt=0; nt<8; nt++){
                int n = wn*64 + nt*8 + g;
                b[nt][0]=Ws[cur][n][kb+tig  ];
                b[nt][1]=Ws[cur][n][kb+tig+4];
            }
            #pragma unroll
            for (int mt=0;mt<2;mt++)
                #pragma unroll
                for (int nt=0;nt<8;nt++)
                    mma8(acc[mt][nt], a[mt], b[nt]);
        }

        if (t + 1 < 64){
            const int nxt = cur ^ 1;
            *(uint4*)&Xs[nxt][srow[0]][sc4[0]*4] = make_uint4(f2tf(xr0.x),f2tf(xr0.y),f2tf(xr0.z),f2tf(xr0.w));
            *(uint4*)&Xs[nxt][srow[1]][sc4[1]*4] = make_uint4(f2tf(xr1.x),f2tf(xr1.y),f2tf(xr1.z),f2tf(xr1.w));
            *(uint4*)&Ws[nxt][srow[0]][sc4[0]*4] = make_uint4(f2tf(wr0.x),f2tf(wr0.y),f2tf(wr0.z),f2tf(wr0.w));
            *(uint4*)&Ws[nxt][srow[1]][sc4[1]*4] = make_uint4(f2tf(wr1.x),f2tf(wr1.y),f2tf(wr1.z),f2tf(wr1.w));
            __syncthreads();
        }
    }

    const int h = (n0 >> 6) + wn;
    #pragma unroll
    for (int mt=0;mt<2;mt++){
        #pragma unroll
        for (int half=0; half<2; half++){
            int m  = m0 + wm*32 + mt*16 + g + half*8;
            int b_ = m >> 11;
            int s  = m & (SS-1);
            float* orow = Out + (((size_t)(b_*HH + h))*SS + s)*DH;
            #pragma unroll
            for (int nt=0; nt<8; nt++){
                int d = nt*8 + tig*2;
                float2 v;
                v.x = acc[mt][nt][half*2+0];
                v.y = acc[mt][nt][half*2+1];
                *(float2*)(orow + d) = v;
            }
        }
    }
}

// ============================================================================
// Flash attention v4: qblock=128, 4 warps, M=32/warp, cp.async double-buffer.
// R12: ONE in-place cvt.rna pass per tile converts K,V fp32 -> tf32 in smem
// (each thread converts its own 16 uint4 chunks; no cross-thread deps).
// Fragment loads in QK/PV are then plain LDS — removes 256 redundant
// per-warp cvt ops per tile from the issue stream and the load->mma chains.
// smem: K[2][64][68] | V[2][64][68] | Pb[128][68]  = 104448 B.
// ============================================================================
#define AT_PAD 68
#define KB_WORDS (64*AT_PAD)
#define VB_BASE  (2*KB_WORDS)
#define PB_BASE  (4*KB_WORDS)
#define AT_SMEM_WORDS (PB_BASE + 128*AT_PAD)
#define AT_SMEM_BYTES (AT_SMEM_WORDS*4)

__global__ __launch_bounds__(128) void attn_kernel(float* __restrict__ out){
    extern __shared__ uint32_t sm[];
    uint32_t* uK = sm;              // [2][64][68] K tiles (fp32 -> tf32 in place)
    uint32_t* uV = sm + VB_BASE;    // [2][64][68] V tiles (fp32 -> tf32 in place)
    uint32_t* Pb = sm + PB_BASE;    // [128][68] Q (tf32), then P (tf32)
    const uint32_t sbase = (uint32_t)__cvta_generic_to_shared(sm);

    const int tid = threadIdx.x;
    const int w   = tid >> 5, lane = tid & 31;
    const int g   = lane >> 2, tig = lane & 3;
    const int q0  = blockIdx.x * 128;
    const int h   = blockIdx.y, b = blockIdx.z;
    const size_t headoff = ((size_t)(b*HH + h))*SS*DH;
    const float* Qg = g_Qh + headoff + (size_t)q0*DH;
    const float* Kg = g_Kh + headoff;
    const float* Vg = g_Vh + headoff;
    const float L2E = 1.44269504088896340736f;
    const float NEG_INF = __int_as_float(0xff800000);

    // Per-thread staging/cvt coordinates (8 chunks of 16B per 64x64 tile)
    int crow[8], cc4[8];
    #pragma unroll
    for (int i=0;i<8;i++){
        int idx = tid + i*128;
        crow[i] = idx >> 4;
        cc4[i]  = idx & 15;
    }

    // ---- Issue tile 0 K/V copies into buffer 0
    #pragma unroll
    for (int i=0;i<8;i++){
        uint32_t so = (uint32_t)(crow[i]*AT_PAD + cc4[i]*4) * 4u;
        cpa16(sbase + so,             Kg + (size_t)crow[i]*DH + cc4[i]*4);
        cpa16(sbase + VB_BASE*4 + so, Vg + (size_t)crow[i]*DH + cc4[i]*4);
    }
    CP_COMMIT();

    // ---- Stage Q (scaled by 0.125, tf32) into Pb: 128 rows x 16 float4
    #pragma unroll
    for (int i=0;i<16;i++){
        int idx = tid + i*128;
        int row = idx >> 4, c4 = idx & 15;
        float4 v = *(const float4*)(Qg + (size_t)row*DH + c4*4);
        *(uint4*)&Pb[row*AT_PAD + c4*4] =
            make_uint4(f2tf(v.x*0.125f), f2tf(v.y*0.125f),
                       f2tf(v.z*0.125f), f2tf(v.w*0.125f));
    }
    __syncthreads();
    uint32_t qa[2][8][4];
    #pragma unroll
    for (int mt=0; mt<2; mt++){
        const int r = w*32 + mt*16;
        #pragma unroll
        for (int ks=0; ks<8; ks++){
            int kb = ks*8;
            qa[mt][ks][0]=Pb[(r+g  )*AT_PAD + kb+tig  ];
            qa[mt][ks][1]=Pb[(r+g+8)*AT_PAD + kb+tig  ];
            qa[mt][ks][2]=Pb[(r+g  )*AT_PAD + kb+tig+4];
            qa[mt][ks][3]=Pb[(r+g+8)*AT_PAD + kb+tig+4];
        }
    }

    float Oacc[2][8][4];
    #pragma unroll
    for (int mt=0;mt<2;mt++)
        #pragma unroll
        for (int nt=0;nt<8;nt++)
            #pragma unroll
            for (int c=0;c<4;c++) Oacc[mt][nt][c]=0.f;
    float mr[2][2] = {{NEG_INF,NEG_INF},{NEG_INF,NEG_INF}};
    float lr[2][2] = {{0.f,0.f},{0.f,0.f}};

    for (int t = 0; t < 32; t++){
        const int cur = t & 1;
        uint32_t* kw = uK + cur*KB_WORDS;
        uint32_t* vw = uV + cur*KB_WORDS;

        CP_WAIT0();          // this thread's tile-t copies complete
        __syncthreads();     // all threads' copies visible; prev compute done

        // ---- Issue tile t+1 into the alternate buffer (overlaps everything)
        if (t + 1 < 32){
            const int nxt = cur ^ 1;
            const float* Kn = Kg + (size_t)(t+1)*64*DH;
            const float* Vn = Vg + (size_t)(t+1)*64*DH;
            #pragma unroll
            for (int i=0;i<8;i++){
                uint32_t so = (uint32_t)(nxt*KB_WORDS + crow[i]*AT_PAD + cc4[i]*4) * 4u;
                cpa16(sbase + so,             Kn + (size_t)crow[i]*DH + cc4[i]*4);
                cpa16(sbase + VB_BASE*4 + so, Vn + (size_t)crow[i]*DH + cc4[i]*4);
            }
            CP_COMMIT();
        }

        // ---- In-place tf32 conversion pass (own chunks; no races)
        #pragma unroll
        for (int i=0;i<8;i++){
            uint32_t off = (uint32_t)(crow[i]*AT_PAD + cc4[i]*4);
            uint4 kv = *(uint4*)&kw[off];
            *(uint4*)&kw[off] = make_uint4(f2tf_u(kv.x), f2tf_u(kv.y),
                                           f2tf_u(kv.z), f2tf_u(kv.w));
            uint4 vv = *(uint4*)&vw[off];
            *(uint4*)&vw[off] = make_uint4(f2tf_u(vv.x), f2tf_u(vv.y),
                                           f2tf_u(vv.z), f2tf_u(vv.w));
        }
        __syncthreads();

        // ---- S = Q K^T : plain LDS fragments, shared across M-tiles
        float S[2][8][4];
        #pragma unroll
        for (int mt=0;mt<2;mt++)
            #pragma unroll
            for (int nt=0;nt<8;nt++)
                #pragma unroll
                for (int c=0;c<4;c++) S[mt][nt][c]=0.f;
        #pragma unroll
        for (int ks=0; ks<8; ks++){
            const int kb = ks*8;
            #pragma unroll
            for (int nt=0; nt<8; nt++){
                uint32_t bfr[2];
                bfr[0]=kw[(nt*8+g)*AT_PAD + kb+tig  ];
                bfr[1]=kw[(nt*8+g)*AT_PAD + kb+tig+4];
                mma8(S[0][nt], qa[0][ks], bfr);
                mma8(S[1][nt], qa[1][ks], bfr);
            }
        }

        // ---- Online softmax per M-tile, then write P (warp-private rows)
        #pragma unroll
        for (int mt=0; mt<2; mt++){
            float rmax0 = NEG_INF, rmax1 = NEG_INF;
            #pragma unroll
            for (int nt=0;nt<8;nt++){
                rmax0 = fmaxf(rmax0, fmaxf(S[mt][nt][0], S[mt][nt][1]));
                rmax1 = fmaxf(rmax1, fmaxf(S[mt][nt][2], S[mt][nt][3]));
            }
            rmax0 = fmaxf(rmax0, __shfl_xor_sync(0xffffffffu, rmax0, 1));
            rmax0 = fmaxf(rmax0, __shfl_xor_sync(0xffffffffu, rmax0, 2));
            rmax1 = fmaxf(rmax1, __shfl_xor_sync(0xffffffffu, rmax1, 1));
            rmax1 = fmaxf(rmax1, __shfl_xor_sync(0xffffffffu, rmax1, 2));
            float mn0 = fmaxf(mr[mt][0], rmax0), mn1 = fmaxf(mr[mt][1], rmax1);
            float al0 = ex2f((mr[mt][0] - mn0)*L2E);
            float al1 = ex2f((mr[mt][1] - mn1)*L2E);
            mr[mt][0] = mn0; mr[mt][1] = mn1;

            float rs0 = 0.f, rs1 = 0.f;
            #pragma unroll
            for (int nt=0;nt<8;nt++){
                S[mt][nt][0] = ex2f((S[mt][nt][0]-mn0)*L2E); rs0 += S[mt][nt][0];
                S[mt][nt][1] = ex2f((S[mt][nt][1]-mn0)*L2E); rs0 += S[mt][nt][1];
                S[mt][nt][2] = ex2f((S[mt][nt][2]-mn1)*L2E); rs1 += S[mt][nt][2];
                S[mt][nt][3] = ex2f((S[mt][nt][3]-mn1)*L2E); rs1 += S[mt][nt][3];
            }
            rs0 += __shfl_xor_sync(0xffffffffu, rs0, 1);
            rs0 += __shfl_xor_sync(0xffffffffu, rs0, 2);
            rs1 += __shfl_xor_sync(0xffffffffu, rs1, 1);
            rs1 += __shfl_xor_sync(0xffffffffu, rs1, 2);
            lr[mt][0] = lr[mt][0]*al0 + rs0;
            lr[mt][1] = lr[mt][1]*al1 + rs1;
            #pragma unroll
            for (int nt=0;nt<8;nt++){
                Oacc[mt][nt][0]*=al0; Oacc[mt][nt][1]*=al0;
                Oacc[mt][nt][2]*=al1; Oacc[mt][nt][3]*=al1;
            }

            const int r = w*32 + mt*16;
            #pragma unroll
            for (int nt=0;nt<8;nt++){
                int c0 = nt*8 + tig*2;
                *(uint2*)&Pb[(r+g  )*AT_PAD + c0] =
                    make_uint2(f2tf(S[mt][nt][0]), f2tf(S[mt][nt][1]));
                *(uint2*)&Pb[(r+g+8)*AT_PAD + c0] =
                    make_uint2(f2tf(S[mt][nt][2]), f2tf(S[mt][nt][3]));
            }
        }
        __syncwarp();

        // ---- O += P V : plain LDS bv from V[s][d] (tf32 in smem)
        #pragma unroll
        for (int ks=0; ks<8; ks++){
            const int kb = ks*8;
            uint32_t pa[2][4];
            #pragma unroll
            for (int mt=0; mt<2; mt++){
                const int r = w*32 + mt*16;
                pa[mt][0]=Pb[(r+g  )*AT_PAD + kb+tig  ];
                pa[mt][1]=Pb[(r+g+8)*AT_PAD + kb+tig  ];
                pa[mt][2]=Pb[(r+g  )*AT_PAD + kb+tig+4];
                pa[mt][3]=Pb[(r+g+8)*AT_PAD + kb+tig+4];
            }
            #pragma unroll
            for (int nt=0; nt<8; nt++){
                uint32_t bv[2];
                bv[0]=vw[(kb+tig  )*AT_PAD + nt*8+g];
                bv[1]=vw[(kb+tig+4)*AT_PAD + nt*8+g];
                mma8(Oacc[0][nt], pa[0], bv);
                mma8(Oacc[1][nt], pa[1], bv);
            }
        }
    }

    // ---- Epilogue: out[b, s, h*64+d] = O / l
    #pragma unroll
    for (int mt=0; mt<2; mt++){
        float inv0 = 1.f / lr[mt][0], inv1 = 1.f / lr[mt][1];
        int s0 = q0 + w*32 + mt*16 + g;
        #pragma unroll
        for (int nt=0;nt<8;nt++){
            int d = nt*8 + tig*2;
            float2 v0; v0.x = Oacc[mt][nt][0]*inv0; v0.y = Oacc[mt][nt][1]*inv0;
            *(float2*)(out + ((size_t)b*SS + s0  )*DDIM + h*DH + d) = v0;
            float2 v1; v1.x = Oacc[mt][nt][2]*inv1; v1.y = Oacc[mt][nt][3]*inv1;
            *(float2*)(out + ((size_t)b*SS + s0+8)*DDIM + h*DH + d) = v1;
        }
    }
}

extern "C" void kernel_launch(void* const* d_in, const int* in_sizes, int n_in,
                              void* d_out, int out_size){
    const float* q  = (const float*)d_in[0];
    const float* k  = (const float*)d_in[1];
    const float* v  = (const float*)d_in[2];
    const float* Wq = (const float*)d_in[3];
    const float* Wk = (const float*)d_in[4];
    const float* Wv = (const float*)d_in[5];

    dim3 pg(DDIM/128, MM/128, 3);  // (8, 64, 3) — fused Q/K/V projections
    proj_kernel<<<pg, 256>>>(q, k, v, Wq, Wk, Wv);

    cudaFuncSetAttribute(attn_kernel,
                         cudaFuncAttributeMaxDynamicSharedMemorySize,
                         AT_SMEM_BYTES);
    dim3 ag(SS/128, HH, BB);       // (16, 16, 4)
    attn_kernel<<<ag, 128, AT_SMEM_BYTES>>>((float*)d_out);
}

// round 14
// speedup vs baseline: 1.1533x; 1.1533x over previous
#include <cuda_runtime.h>
#include <cuda_bf16.h>
#include <cstdint>

#define BB 4
#define SS 2048
#define DDIM 1024
#define HH 16
#define DH 64
#define MM (BB*SS)

// Head-major scratch [B,H,S,Dh] — holds TF32 bit patterns (pre-converted by proj)
__device__ float g_Qh[(size_t)BB*HH*SS*DH];
__device__ float g_Kh[(size_t)BB*HH*SS*DH];
__device__ float g_Vh[(size_t)BB*HH*SS*DH];

__device__ __forceinline__ uint32_t f2tf(float x){
    uint32_t y; asm("cvt.rna.tf32.f32 %0, %1;" : "=r"(y) : "f"(x)); return y;
}
__device__ __forceinline__ float ex2f(float x){
    float y; asm("ex2.approx.ftz.f32 %0, %1;" : "=f"(y) : "f"(x)); return y;
}
__device__ __forceinline__ void mma8(float* d, const uint32_t* a, const uint32_t* b){
    asm volatile(
        "mma.sync.aligned.m16n8k8.row.col.f32.tf32.tf32.f32 "
        "{%0,%1,%2,%3},{%4,%5,%6,%7},{%8,%9},{%0,%1,%2,%3};\n"
        : "+f"(d[0]), "+f"(d[1]), "+f"(d[2]), "+f"(d[3])
        : "r"(a[0]), "r"(a[1]), "r"(a[2]), "r"(a[3]), "r"(b[0]), "r"(b[1]));
}
__device__ __forceinline__ void cpa16(uint32_t dst, const float* src){
    asm volatile("cp.async.ca.shared.global [%0], [%1], 16;" :: "r"(dst), "l"(src));
}
#define CP_COMMIT() asm volatile("cp.async.commit_group;" ::: "memory")
#define CP_WAIT0()  asm volatile("cp.async.wait_group 0;" ::: "memory")

// ============================================================================
// Projection v4: CTA tile 128x128, BK=16, 8 warps, double-buffered k-loop
// (unchanged loop from R10/R11 pass). R13/R14: epilogue PRE-CONVERTS outputs
// to tf32 (Q additionally pre-scaled by 1/sqrt(64)=0.125) so attn needs NO cvt.
// ============================================================================
__global__ __launch_bounds__(256, 2) void proj_kernel(const float* __restrict__ Xq,
                                                      const float* __restrict__ Xk,
                                                      const float* __restrict__ Xv,
                                                      const float* __restrict__ Wq,
                                                      const float* __restrict__ Wk,
                                                      const float* __restrict__ Wv){
    __shared__ uint32_t Xs[2][128][20];
    __shared__ uint32_t Ws[2][128][20];

    const int which = blockIdx.z;
    const float* X = (which == 0) ? Xq : (which == 1) ? Xk : Xv;
    const float* W = (which == 0) ? Wq : (which == 1) ? Wk : Wv;
    float* Out     = (which == 0) ? g_Qh : (which == 1) ? g_Kh : g_Vh;
    const float oscale = (which == 0) ? 0.125f : 1.0f;

    const int tid  = threadIdx.x;
    const int wid  = tid >> 5, lane = tid & 31;
    const int g    = lane >> 2, tig = lane & 3;
    const int wm   = wid & 3,  wn  = wid >> 2;
    const int m0   = blockIdx.y * 128;
    const int n0   = blockIdx.x * 128;

    int srow[2], sc4[2];
    #pragma unroll
    for (int i=0;i<2;i++){
        int idx = tid + i*256;
        srow[i] = idx >> 2;
        sc4[i]  = idx & 3;
    }
    const float* Xrow0 = X + (size_t)(m0+srow[0])*DDIM + sc4[0]*4;
    const float* Xrow1 = X + (size_t)(m0+srow[1])*DDIM + sc4[1]*4;
    const float* Wrow0 = W + (size_t)(n0+srow[0])*DDIM + sc4[0]*4;
    const float* Wrow1 = W + (size_t)(n0+srow[1])*DDIM + sc4[1]*4;

    float acc[2][8][4];
    #pragma unroll
    for (int i=0;i<2;i++)
        #pragma unroll
        for (int j=0;j<8;j++)
            #pragma unroll
            for (int c=0;c<4;c++) acc[i][j][c]=0.f;

    float4 xr0 = *(const float4*)(Xrow0);
    float4 xr1 = *(const float4*)(Xrow1);
    float4 wr0 = *(const float4*)(Wrow0);
    float4 wr1 = *(const float4*)(Wrow1);
    *(uint4*)&Xs[0][srow[0]][sc4[0]*4] = make_uint4(f2tf(xr0.x),f2tf(xr0.y),f2tf(xr0.z),f2tf(xr0.w));
    *(uint4*)&Xs[0][srow[1]][sc4[1]*4] = make_uint4(f2tf(xr1.x),f2tf(xr1.y),f2tf(xr1.z),f2tf(xr1.w));
    *(uint4*)&Ws[0][srow[0]][sc4[0]*4] = make_uint4(f2tf(wr0.x),f2tf(wr0.y),f2tf(wr0.z),f2tf(wr0.w));
    *(uint4*)&Ws[0][srow[1]][sc4[1]*4] = make_uint4(f2tf(wr1.x),f2tf(wr1.y),f2tf(wr1.z),f2tf(wr1.w));
    __syncthreads();

    for (int t = 0; t < 64; t++){
        const int cur = t & 1;
        if (t + 1 < 64){
            const int kt = (t + 1) * 16;
            xr0 = *(const float4*)(Xrow0 + kt);
            xr1 = *(const float4*)(Xrow1 + kt);
            wr0 = *(const float4*)(Wrow0 + kt);
            wr1 = *(const float4*)(Wrow1 + kt);
        }

        #pragma unroll
        for (int ks=0; ks<2; ks++){
            const int kb = ks*8;
            uint32_t a[2][4], b[8][2];
            #pragma unroll
            for (int mt=0; mt<2; mt++){
                int r = wm*32 + mt*16;
                a[mt][0]=Xs[cur][r+g  ][kb+tig  ];
                a[mt][1]=Xs[cur][r+g+8][kb+tig  ];
                a[mt][2]=Xs[cur][r+g  ][kb+tig+4];
                a[mt][3]=Xs[cur][r+g+8][kb+tig+4];
            }
            #pragma unroll
            for (int nt=0; nt<8; nt++){
                int n = wn*64 + nt*8 + g;
                b[nt][0]=Ws[cur][n][kb+tig  ];
                b[nt][1]=Ws[cur][n][kb+tig+4];
            }
            #pragma unroll
            for (int mt=0;mt<2;mt++)
                #pragma unroll
                for (int nt=0;nt<8;nt++)
                    mma8(acc[mt][nt], a[mt], b[nt]);
        }

        if (t + 1 < 64){
            const int nxt = cur ^ 1;
            *(uint4*)&Xs[nxt][srow[0]][sc4[0]*4] = make_uint4(f2tf(xr0.x),f2tf(xr0.y),f2tf(xr0.z),f2tf(xr0.w));
            *(uint4*)&Xs[nxt][srow[1]][sc4[1]*4] = make_uint4(f2tf(xr1.x),f2tf(xr1.y),f2tf(xr1.z),f2tf(xr1.w));
            *(uint4*)&Ws[nxt][srow[0]][sc4[0]*4] = make_uint4(f2tf(wr0.x),f2tf(wr0.y),f2tf(wr0.z),f2tf(wr0.w));
            *(uint4*)&Ws[nxt][srow[1]][sc4[1]*4] = make_uint4(f2tf(wr1.x),f2tf(wr1.y),f2tf(wr1.z),f2tf(wr1.w));
            __syncthreads();
        }
    }

    // Epilogue: head-major store, PRE-CONVERTED to tf32 (Q pre-scaled 0.125).
    const int h = (n0 >> 6) + wn;
    #pragma unroll
    for (int mt=0;mt<2;mt++){
        #pragma unroll
        for (int half=0; half<2; half++){
            int m  = m0 + wm*32 + mt*16 + g + half*8;
            int b_ = m >> 11;
            int s  = m & (SS-1);
            float* orow = Out + (((size_t)(b_*HH + h))*SS + s)*DH;
            #pragma unroll
            for (int nt=0; nt<8; nt++){
                int d = nt*8 + tig*2;
                float2 v;
                v.x = __uint_as_float(f2tf(acc[mt][nt][half*2+0]*oscale));
                v.y = __uint_as_float(f2tf(acc[mt][nt][half*2+1]*oscale));
                *(float2*)(orow + d) = v;
            }
        }
    }
}

// ============================================================================
// Flash attention v5 (= R11 structure, zero-cvt data path):
// qblock=128, 4 warps, M=32/warp, cp.async double-buffered K/V.
// Scratch arrives PRE-CONVERTED to tf32 (Q pre-scaled) -> all K/V/Q fragment
// loads are plain LDS; only P (computed here) needs f2tf.
// V raw [s][d] layout -> PV B-loads ~2-way conflicted (accepted, as in R11).
// smem: K[2][64][68] | V[2][64][68] | Pb[128][68]  = 104448 B.
// ============================================================================
#define AT_PAD 68
#define KB_WORDS (64*AT_PAD)
#define VB_BASE  (2*KB_WORDS)
#define PB_BASE  (4*KB_WORDS)
#define AT_SMEM_WORDS (PB_BASE + 128*AT_PAD)
#define AT_SMEM_BYTES (AT_SMEM_WORDS*4)

__global__ __launch_bounds__(128) void attn_kernel(float* __restrict__ out){
    extern __shared__ uint32_t sm[];
    uint32_t* uK = sm;              // [2][64][68] K tiles (tf32)
    uint32_t* uV = sm + VB_BASE;    // [2][64][68] V tiles (tf32)
    uint32_t* Pb = sm + PB_BASE;    // [128][68] Q (tf32), then P (tf32)
    const uint32_t sbase = (uint32_t)__cvta_generic_to_shared(sm);

    const int tid = threadIdx.x;
    const int w   = tid >> 5, lane = tid & 31;
    const int g   = lane >> 2, tig = lane & 3;
    const int q0  = blockIdx.x * 128;
    const int h   = blockIdx.y, b = blockIdx.z;
    const size_t headoff = ((size_t)(b*HH + h))*SS*DH;
    const float* Qg = g_Qh + headoff + (size_t)q0*DH;
    const float* Kg = g_Kh + headoff;
    const float* Vg = g_Vh + headoff;
    const float L2E = 1.44269504088896340736f;
    const float NEG_INF = __int_as_float(0xff800000);

    // Per-thread staging coordinates (8 chunks of 16B per 64x64 tile)
    int crow[8], cc4[8];
    #pragma unroll
    for (int i=0;i<8;i++){
        int idx = tid + i*128;
        crow[i] = idx >> 4;
        cc4[i]  = idx & 15;
    }

    // ---- Issue tile 0 K/V copies into buffer 0
    #pragma unroll
    for (int i=0;i<8;i++){
        uint32_t so = (uint32_t)(crow[i]*AT_PAD + cc4[i]*4) * 4u;
        cpa16(sbase + so,             Kg + (size_t)crow[i]*DH + cc4[i]*4);
        cpa16(sbase + VB_BASE*4 + so, Vg + (size_t)crow[i]*DH + cc4[i]*4);
    }
    CP_COMMIT();

    // ---- Stage Q (already tf32 + scaled): plain 16B copies
    #pragma unroll
    for (int i=0;i<16;i++){
        int idx = tid + i*128;
        int row = idx >> 4, c4 = idx & 15;
        *(uint4*)&Pb[row*AT_PAD + c4*4] =
            *(const uint4*)(Qg + (size_t)row*DH + c4*4);
    }
    __syncthreads();
    uint32_t qa[2][8][4];
    #pragma unroll
    for (int mt=0; mt<2; mt++){
        const int r = w*32 + mt*16;
        #pragma unroll
        for (int ks=0; ks<8; ks++){
            int kb = ks*8;
            qa[mt][ks][0]=Pb[(r+g  )*AT_PAD + kb+tig  ];
            qa[mt][ks][1]=Pb[(r+g+8)*AT_PAD + kb+tig  ];
            qa[mt][ks][2]=Pb[(r+g  )*AT_PAD + kb+tig+4];
            qa[mt][ks][3]=Pb[(r+g+8)*AT_PAD + kb+tig+4];
        }
    }

    float Oacc[2][8][4];
    #pragma unroll
    for (int mt=0;mt<2;mt++)
        #pragma unroll
        for (int nt=0;nt<8;nt++)
            #pragma unroll
            for (int c=0;c<4;c++) Oacc[mt][nt][c]=0.f;
    float mr[2][2] = {{NEG_INF,NEG_INF},{NEG_INF,NEG_INF}};
    float lr[2][2] = {{0.f,0.f},{0.f,0.f}};

    for (int t = 0; t < 32; t++){
        const int cur = t & 1;
        const uint32_t* kw = uK + cur*KB_WORDS;
        const uint32_t* vw = uV + cur*KB_WORDS;

        CP_WAIT0();          // tile-t copies complete
        __syncthreads();     // all threads' copies visible; prev compute done

        // ---- Issue tile t+1 into the alternate buffer (overlaps compute)
        if (t + 1 < 32){
            const int nxt = cur ^ 1;
            const float* Kn = Kg + (size_t)(t+1)*64*DH;
            const float* Vn = Vg + (size_t)(t+1)*64*DH;
            #pragma unroll
            for (int i=0;i<8;i++){
                uint32_t so = (uint32_t)(nxt*KB_WORDS + crow[i]*AT_PAD + cc4[i]*4) * 4u;
                cpa16(sbase + so,             Kn + (size_t)crow[i]*DH + cc4[i]*4);
                cpa16(sbase + VB_BASE*4 + so, Vn + (size_t)crow[i]*DH + cc4[i]*4);
            }
            CP_COMMIT();
        }

        // ---- S = Q K^T : plain LDS fragments, shared across M-tiles
        float S[2][8][4];
        #pragma unroll
        for (int mt=0;mt<2;mt++)
            #pragma unroll
            for (int nt=0;nt<8;nt++)
                #pragma unroll
                for (int c=0;c<4;c++) S[mt][nt][c]=0.f;
        #pragma unroll
        for (int ks=0; ks<8; ks++){
            const int kb = ks*8;
            #pragma unroll
            for (int nt=0; nt<8; nt++){
                uint32_t bfr[2];
                bfr[0]=kw[(nt*8+g)*AT_PAD + kb+tig  ];
                bfr[1]=kw[(nt*8+g)*AT_PAD + kb+tig+4];
                mma8(S[0][nt], qa[0][ks], bfr);
                mma8(S[1][nt], qa[1][ks], bfr);
            }
        }

        // ---- Online softmax per M-tile, then write P (warp-private rows)
        #pragma unroll
        for (int mt=0; mt<2; mt++){
            float rmax0 = NEG_INF, rmax1 = NEG_INF;
            #pragma unroll
            for (int nt=0;nt<8;nt++){
                rmax0 = fmaxf(rmax0, fmaxf(S[mt][nt][0], S[mt][nt][1]));
                rmax1 = fmaxf(rmax1, fmaxf(S[mt][nt][2], S[mt][nt][3]));
            }
            rmax0 = fmaxf(rmax0, __shfl_xor_sync(0xffffffffu, rmax0, 1));
            rmax0 = fmaxf(rmax0, __shfl_xor_sync(0xffffffffu, rmax0, 2));
            rmax1 = fmaxf(rmax1, __shfl_xor_sync(0xffffffffu, rmax1, 1));
            rmax1 = fmaxf(rmax1, __shfl_xor_sync(0xffffffffu, rmax1, 2));
            float mn0 = fmaxf(mr[mt][0], rmax0), mn1 = fmaxf(mr[mt][1], rmax1);
            float al0 = ex2f((mr[mt][0] - mn0)*L2E);
            float al1 = ex2f((mr[mt][1] - mn1)*L2E);
            mr[mt][0] = mn0; mr[mt][1] = mn1;

            float rs0 = 0.f, rs1 = 0.f;
            #pragma unroll
            for (int nt=0;nt<8;nt++){
                S[mt][nt][0] = ex2f((S[mt][nt][0]-mn0)*L2E); rs0 += S[mt][nt][0];
                S[mt][nt][1] = ex2f((S[mt][nt][1]-mn0)*L2E); rs0 += S[mt][nt][1];
                S[mt][nt][2] = ex2f((S[mt][nt][2]-mn1)*L2E); rs1 += S[mt][nt][2];
                S[mt][nt][3] = ex2f((S[mt][nt][3]-mn1)*L2E); rs1 += S[mt][nt][3];
            }
            rs0 += __shfl_xor_sync(0xffffffffu, rs0, 1);
            rs0 += __shfl_xor_sync(0xffffffffu, rs0, 2);
            rs1 += __shfl_xor_sync(0xffffffffu, rs1, 1);
            rs1 += __shfl_xor_sync(0xffffffffu, rs1, 2);
            lr[mt][0] = lr[mt][0]*al0 + rs0;
            lr[mt][1] = lr[mt][1]*al1 + rs1;
            #pragma unroll
            for (int nt=0;nt<8;nt++){
                Oacc[mt][nt][0]*=al0; Oacc[mt][nt][1]*=al0;
                Oacc[mt][nt][2]*=al1; Oacc[mt][nt][3]*=al1;
            }

            const int r = w*32 + mt*16;
            #pragma unroll
            for (int nt=0;nt<8;nt++){
                int c0 = nt*8 + tig*2;
                *(uint2*)&Pb[(r+g  )*AT_PAD + c0] =
                    make_uint2(f2tf(S[mt][nt][0]), f2tf(S[mt][nt][1]));
                *(uint2*)&Pb[(r+g+8)*AT_PAD + c0] =
                    make_uint2(f2tf(S[mt][nt][2]), f2tf(S[mt][nt][3]));
            }
        }
        __syncwarp();

        // ---- O += P V : plain LDS bv from V[s][d] (tf32)
        #pragma unroll
        for (int ks=0; ks<8; ks++){
            const int kb = ks*8;
            uint32_t pa[2][4];
            #pragma unroll
            for (int mt=0; mt<2; mt++){
                const int r = w*32 + mt*16;
                pa[mt][0]=Pb[(r+g  )*AT_PAD + kb+tig  ];
                pa[mt][1]=Pb[(r+g+8)*AT_PAD + kb+tig  ];
                pa[mt][2]=Pb[(r+g  )*AT_PAD + kb+tig+4];
                pa[mt][3]=Pb[(r+g+8)*AT_PAD + kb+tig+4];
            }
            #pragma unroll
            for (int nt=0; nt<8; nt++){
                uint32_t bv[2];
                bv[0]=vw[(kb+tig  )*AT_PAD + nt*8+g];
                bv[1]=vw[(kb+tig+4)*AT_PAD + nt*8+g];
                mma8(Oacc[0][nt], pa[0], bv);
                mma8(Oacc[1][nt], pa[1], bv);
            }
        }
    }

    // ---- Epilogue: out[b, s, h*64+d] = O / l
    #pragma unroll
    for (int mt=0; mt<2; mt++){
        float inv0 = 1.f / lr[mt][0], inv1 = 1.f / lr[mt][1];
        int s0 = q0 + w*32 + mt*16 + g;
        #pragma unroll
        for (int nt=0;nt<8;nt++){
            int d = nt*8 + tig*2;
            float2 v0; v0.x = Oacc[mt][nt][0]*inv0; v0.y = Oacc[mt][nt][1]*inv0;
            *(float2*)(out + ((size_t)b*SS + s0  )*DDIM + h*DH + d) = v0;
            float2 v1; v1.x = Oacc[mt][nt][2]*inv1; v1.y = Oacc[mt][nt][3]*inv1;
            *(float2*)(out + ((size_t)b*SS + s0+8)*DDIM + h*DH + d) = v1;
        }
    }
}

extern "C" void kernel_launch(void* const* d_in, const int* in_sizes, int n_in,
                              void* d_out, int out_size){
    const float* q  = (const float*)d_in[0];
    const float* k  = (const float*)d_in[1];
    const float* v  = (const float*)d_in[2];
    const float* Wq = (const float*)d_in[3];
    const float* Wk = (const float*)d_in[4];
    const float* Wv = (const float*)d_in[5];

    dim3 pg(DDIM/128, MM/128, 3);  // (8, 64, 3) — fused Q/K/V projections
    proj_kernel<<<pg, 256>>>(q, k, v, Wq, Wk, Wv);

    cudaFuncSetAttribute(attn_kernel,
                         cudaFuncAttributeMaxDynamicSharedMemorySize,
                         AT_SMEM_BYTES);
    dim3 ag(SS/128, HH, BB);       // (16, 16, 4)
    attn_kernel<<<ag, 128, AT_SMEM_BYTES>>>((float*)d_out);
}

// round 15
// speedup vs baseline: 1.1604x; 1.0061x over previous
#include <cuda_runtime.h>
#include <cuda_bf16.h>
#include <cstdint>

#define BB 4
#define SS 2048
#define DDIM 1024
#define HH 16
#define DH 64
#define MM (BB*SS)

// Scratch (tf32 bit patterns, pre-converted by proj):
//   g_Qh, g_Kh : head-major [B,H,S,Dh]   (Q pre-scaled by 0.125)
//   g_Vh       : TRANSPOSED  [B,H,Dh,S]  -> attn PV B-loads conflict-free
__device__ float g_Qh[(size_t)BB*HH*SS*DH];
__device__ float g_Kh[(size_t)BB*HH*SS*DH];
__device__ float g_Vh[(size_t)BB*HH*SS*DH];

__device__ __forceinline__ uint32_t f2tf(float x){
    uint32_t y; asm("cvt.rna.tf32.f32 %0, %1;" : "=r"(y) : "f"(x)); return y;
}
__device__ __forceinline__ float ex2f(float x){
    float y; asm("ex2.approx.ftz.f32 %0, %1;" : "=f"(y) : "f"(x)); return y;
}
__device__ __forceinline__ void mma8(float* d, const uint32_t* a, const uint32_t* b){
    asm volatile(
        "mma.sync.aligned.m16n8k8.row.col.f32.tf32.tf32.f32 "
        "{%0,%1,%2,%3},{%4,%5,%6,%7},{%8,%9},{%0,%1,%2,%3};\n"
        : "+f"(d[0]), "+f"(d[1]), "+f"(d[2]), "+f"(d[3])
        : "r"(a[0]), "r"(a[1]), "r"(a[2]), "r"(a[3]), "r"(b[0]), "r"(b[1]));
}
__device__ __forceinline__ void cpa16(uint32_t dst, const float* src){
    asm volatile("cp.async.cg.shared.global [%0], [%1], 16;" :: "r"(dst), "l"(src));
}
#define CP_COMMIT() asm volatile("cp.async.commit_group;" ::: "memory")
#define CP_WAIT0()  asm volatile("cp.async.wait_group 0;" ::: "memory")

// ============================================================================
// Projection v5: CTA tile 128x128, BK=16, 8 warps, double-buffered k-loop.
// Epilogue pre-converts to tf32 (Q pre-scaled 0.125). R15: V is stored
// TRANSPOSED [B,H,Dh,S] (scalar stores; 8 consecutive lanes per 32B sector).
// ============================================================================
__global__ __launch_bounds__(256, 2) void proj_kernel(const float* __restrict__ Xq,
                                                      const float* __restrict__ Xk,
                                                      const float* __restrict__ Xv,
                                                      const float* __restrict__ Wq,
                                                      const float* __restrict__ Wk,
                                                      const float* __restrict__ Wv){
    __shared__ uint32_t Xs[2][128][20];
    __shared__ uint32_t Ws[2][128][20];

    const int which = blockIdx.z;
    const float* X = (which == 0) ? Xq : (which == 1) ? Xk : Xv;
    const float* W = (which == 0) ? Wq : (which == 1) ? Wk : Wv;
    float* Out     = (which == 0) ? g_Qh : (which == 1) ? g_Kh : g_Vh;
    const float oscale = (which == 0) ? 0.125f : 1.0f;

    const int tid  = threadIdx.x;
    const int wid  = tid >> 5, lane = tid & 31;
    const int g    = lane >> 2, tig = lane & 3;
    const int wm   = wid & 3,  wn  = wid >> 2;
    const int m0   = blockIdx.y * 128;
    const int n0   = blockIdx.x * 128;

    int srow[2], sc4[2];
    #pragma unroll
    for (int i=0;i<2;i++){
        int idx = tid + i*256;
        srow[i] = idx >> 2;
        sc4[i]  = idx & 3;
    }
    const float* Xrow0 = X + (size_t)(m0+srow[0])*DDIM + sc4[0]*4;
    const float* Xrow1 = X + (size_t)(m0+srow[1])*DDIM + sc4[1]*4;
    const float* Wrow0 = W + (size_t)(n0+srow[0])*DDIM + sc4[0]*4;
    const float* Wrow1 = W + (size_t)(n0+srow[1])*DDIM + sc4[1]*4;

    float acc[2][8][4];
    #pragma unroll
    for (int i=0;i<2;i++)
        #pragma unroll
        for (int j=0;j<8;j++)
            #pragma unroll
            for (int c=0;c<4;c++) acc[i][j][c]=0.f;

    float4 xr0 = *(const float4*)(Xrow0);
    float4 xr1 = *(const float4*)(Xrow1);
    float4 wr0 = *(const float4*)(Wrow0);
    float4 wr1 = *(const float4*)(Wrow1);
    *(uint4*)&Xs[0][srow[0]][sc4[0]*4] = make_uint4(f2tf(xr0.x),f2tf(xr0.y),f2tf(xr0.z),f2tf(xr0.w));
    *(uint4*)&Xs[0][srow[1]][sc4[1]*4] = make_uint4(f2tf(xr1.x),f2tf(xr1.y),f2tf(xr1.z),f2tf(xr1.w));
    *(uint4*)&Ws[0][srow[0]][sc4[0]*4] = make_uint4(f2tf(wr0.x),f2tf(wr0.y),f2tf(wr0.z),f2tf(wr0.w));
    *(uint4*)&Ws[0][srow[1]][sc4[1]*4] = make_uint4(f2tf(wr1.x),f2tf(wr1.y),f2tf(wr1.z),f2tf(wr1.w));
    __syncthreads();

    for (int t = 0; t < 64; t++){
        const int cur = t & 1;
        if (t + 1 < 64){
            const int kt = (t + 1) * 16;
            xr0 = *(const float4*)(Xrow0 + kt);
            xr1 = *(const float4*)(Xrow1 + kt);
            wr0 = *(const float4*)(Wrow0 + kt);
            wr1 = *(const float4*)(Wrow1 + kt);
        }

        #pragma unroll
        for (int ks=0; ks<2; ks++){
            const int kb = ks*8;
            uint32_t a[2][4], b[8][2];
            #pragma unroll
            for (int mt=0; mt<2; mt++){
                int r = wm*32 + mt*16;
                a[mt][0]=Xs[cur][r+g  ][kb+tig  ];
                a[mt][1]=Xs[cur][r+g+8][kb+tig  ];
                a[mt][2]=Xs[cur][r+g  ][kb+tig+4];
                a[mt][3]=Xs[cur][r+g+8][kb+tig+4];
            }
            #pragma unroll
            for (int nt=0; nt<8; nt++){
                int n = wn*64 + nt*8 + g;
                b[nt][0]=Ws[cur][n][kb+tig  ];
                b[nt][1]=Ws[cur][n][kb+tig+4];
            }
            #pragma unroll
            for (int mt=0;mt<2;mt++)
                #pragma unroll
                for (int nt=0;nt<8;nt++)
                    mma8(acc[mt][nt], a[mt], b[nt]);
        }

        if (t + 1 < 64){
            const int nxt = cur ^ 1;
            *(uint4*)&Xs[nxt][srow[0]][sc4[0]*4] = make_uint4(f2tf(xr0.x),f2tf(xr0.y),f2tf(xr0.z),f2tf(xr0.w));
            *(uint4*)&Xs[nxt][srow[1]][sc4[1]*4] = make_uint4(f2tf(xr1.x),f2tf(xr1.y),f2tf(xr1.z),f2tf(xr1.w));
            *(uint4*)&Ws[nxt][srow[0]][sc4[0]*4] = make_uint4(f2tf(wr0.x),f2tf(wr0.y),f2tf(wr0.z),f2tf(wr0.w));
            *(uint4*)&Ws[nxt][srow[1]][sc4[1]*4] = make_uint4(f2tf(wr1.x),f2tf(wr1.y),f2tf(wr1.z),f2tf(wr1.w));
            __syncthreads();
        }
    }

    // Epilogue: pre-converted tf32 stores.
    // Q/K: head-major [b,h,s,d] float2.  V: transposed [b,h,d,s] scalars.
    const int h = (n0 >> 6) + wn;
    #pragma unroll
    for (int mt=0;mt<2;mt++){
        #pragma unroll
        for (int half=0; half<2; half++){
            int m  = m0 + wm*32 + mt*16 + g + half*8;
            int b_ = m >> 11;
            int s  = m & (SS-1);
            if (which != 2){
                float* orow = Out + (((size_t)(b_*HH + h))*SS + s)*DH;
                #pragma unroll
                for (int nt=0; nt<8; nt++){
                    int d = nt*8 + tig*2;
                    float2 v;
                    v.x = __uint_as_float(f2tf(acc[mt][nt][half*2+0]*oscale));
                    v.y = __uint_as_float(f2tf(acc[mt][nt][half*2+1]*oscale));
                    *(float2*)(orow + d) = v;
                }
            } else {
                float* obase = Out + ((size_t)(b_*HH + h))*DH*SS;
                #pragma unroll
                for (int nt=0; nt<8; nt++){
                    int d = nt*8 + tig*2;
                    obase[(size_t)(d  )*SS + s] =
                        __uint_as_float(f2tf(acc[mt][nt][half*2+0]));
                    obase[(size_t)(d+1)*SS + s] =
                        __uint_as_float(f2tf(acc[mt][nt][half*2+1]));
                }
            }
        }
    }
}

// ============================================================================
// Flash attention v6: qblock=128, 4 warps, M=32/warp, cp.async(.cg)
// double-buffered K/V. V scratch is transposed [Dh,S] -> V tiles land as
// [d][s] and PV B-loads use the conflict-free (4g+tig) pattern.
// Zero cvt on K/V/Q (pre-converted); only P needs f2tf.
// smem: K[2][64][68] | Vt[2][64][68] | Pb[128][68]  = 104448 B.
// ============================================================================
#define AT_PAD 68
#define KB_WORDS (64*AT_PAD)
#define VB_BASE  (2*KB_WORDS)
#define PB_BASE  (4*KB_WORDS)
#define AT_SMEM_WORDS (PB_BASE + 128*AT_PAD)
#define AT_SMEM_BYTES (AT_SMEM_WORDS*4)

__global__ __launch_bounds__(128) void attn_kernel(float* __restrict__ out){
    extern __shared__ uint32_t sm[];
    uint32_t* uK = sm;              // [2][64][68] K tiles [s][k] (tf32)
    uint32_t* uV = sm + VB_BASE;    // [2][64][68] V tiles [d][s] (tf32)
    uint32_t* Pb = sm + PB_BASE;    // [128][68] Q (tf32), then P (tf32)
    const uint32_t sbase = (uint32_t)__cvta_generic_to_shared(sm);

    const int tid = threadIdx.x;
    const int w   = tid >> 5, lane = tid & 31;
    const int g   = lane >> 2, tig = lane & 3;
    const int q0  = blockIdx.x * 128;
    const int h   = blockIdx.y, b = blockIdx.z;
    const size_t headoff = ((size_t)(b*HH + h))*SS*DH;
    const float* Qg = g_Qh + headoff + (size_t)q0*DH;
    const float* Kg = g_Kh + headoff;
    const float* Vg = g_Vh + headoff;          // layout [Dh][S]
    const float L2E = 1.44269504088896340736f;
    const float NEG_INF = __int_as_float(0xff800000);

    // Per-thread staging coordinates (8 chunks of 16B per 64x64 tile)
    int crow[8], cc4[8];
    #pragma unroll
    for (int i=0;i<8;i++){
        int idx = tid + i*128;
        crow[i] = idx >> 4;
        cc4[i]  = idx & 15;
    }

    // ---- Issue tile 0 K/V copies into buffer 0
    #pragma unroll
    for (int i=0;i<8;i++){
        uint32_t so = (uint32_t)(crow[i]*AT_PAD + cc4[i]*4) * 4u;
        cpa16(sbase + so,             Kg + (size_t)crow[i]*DH + cc4[i]*4);
        cpa16(sbase + VB_BASE*4 + so, Vg + (size_t)crow[i]*SS + cc4[i]*4);
    }
    CP_COMMIT();

    // ---- Stage Q (already tf32 + scaled): plain 16B copies
    #pragma unroll
    for (int i=0;i<16;i++){
        int idx = tid + i*128;
        int row = idx >> 4, c4 = idx & 15;
        *(uint4*)&Pb[row*AT_PAD + c4*4] =
            *(const uint4*)(Qg + (size_t)row*DH + c4*4);
    }
    __syncthreads();
    uint32_t qa[2][8][4];
    #pragma unroll
    for (int mt=0; mt<2; mt++){
        const int r = w*32 + mt*16;
        #pragma unroll
        for (int ks=0; ks<8; ks++){
            int kb = ks*8;
            qa[mt][ks][0]=Pb[(r+g  )*AT_PAD + kb+tig  ];
            qa[mt][ks][1]=Pb[(r+g+8)*AT_PAD + kb+tig  ];
            qa[mt][ks][2]=Pb[(r+g  )*AT_PAD + kb+tig+4];
            qa[mt][ks][3]=Pb[(r+g+8)*AT_PAD + kb+tig+4];
        }
    }

    float Oacc[2][8][4];
    #pragma unroll
    for (int mt=0;mt<2;mt++)
        #pragma unroll
        for (int nt=0;nt<8;nt++)
            #pragma unroll
            for (int c=0;c<4;c++) Oacc[mt][nt][c]=0.f;
    float mr[2][2] = {{NEG_INF,NEG_INF},{NEG_INF,NEG_INF}};
    float lr[2][2] = {{0.f,0.f},{0.f,0.f}};

    for (int t = 0; t < 32; t++){
        const int cur = t & 1;
        const uint32_t* kw = uK + cur*KB_WORDS;
        const uint32_t* vw = uV + cur*KB_WORDS;

        CP_WAIT0();          // tile-t copies complete
        __syncthreads();     // all threads' copies visible; prev compute done

        // ---- Issue tile t+1 into the alternate buffer (overlaps compute)
        if (t + 1 < 32){
            const int nxt = cur ^ 1;
            const float* Kn = Kg + (size_t)(t+1)*64*DH;
            const float* Vn = Vg + (size_t)(t+1)*64;   // s-offset in [Dh][S]
            #pragma unroll
            for (int i=0;i<8;i++){
                uint32_t so = (uint32_t)(nxt*KB_WORDS + crow[i]*AT_PAD + cc4[i]*4) * 4u;
                cpa16(sbase + so,             Kn + (size_t)crow[i]*DH + cc4[i]*4);
                cpa16(sbase + VB_BASE*4 + so, Vn + (size_t)crow[i]*SS + cc4[i]*4);
            }
            CP_COMMIT();
        }

        // ---- S = Q K^T : plain LDS fragments, shared across M-tiles
        float S[2][8][4];
        #pragma unroll
        for (int mt=0;mt<2;mt++)
            #pragma unroll
            for (int nt=0;nt<8;nt++)
                #pragma unroll
                for (int c=0;c<4;c++) S[mt][nt][c]=0.f;
        #pragma unroll
        for (int ks=0; ks<8; ks++){
            const int kb = ks*8;
            #pragma unroll
            for (int nt=0; nt<8; nt++){
                uint32_t bfr[2];
                bfr[0]=kw[(nt*8+g)*AT_PAD + kb+tig  ];
                bfr[1]=kw[(nt*8+g)*AT_PAD + kb+tig+4];
                mma8(S[0][nt], qa[0][ks], bfr);
                mma8(S[1][nt], qa[1][ks], bfr);
            }
        }

        // ---- Online softmax per M-tile, then write P (warp-private rows)
        #pragma unroll
        for (int mt=0; mt<2; mt++){
            float rmax0 = NEG_INF, rmax1 = NEG_INF;
            #pragma unroll
            for (int nt=0;nt<8;nt++){
                rmax0 = fmaxf(rmax0, fmaxf(S[mt][nt][0], S[mt][nt][1]));
                rmax1 = fmaxf(rmax1, fmaxf(S[mt][nt][2], S[mt][nt][3]));
            }
            rmax0 = fmaxf(rmax0, __shfl_xor_sync(0xffffffffu, rmax0, 1));
            rmax0 = fmaxf(rmax0, __shfl_xor_sync(0xffffffffu, rmax0, 2));
            rmax1 = fmaxf(rmax1, __shfl_xor_sync(0xffffffffu, rmax1, 1));
            rmax1 = fmaxf(rmax1, __shfl_xor_sync(0xffffffffu, rmax1, 2));
            float mn0 = fmaxf(mr[mt][0], rmax0), mn1 = fmaxf(mr[mt][1], rmax1);
            float al0 = ex2f((mr[mt][0] - mn0)*L2E);
            float al1 = ex2f((mr[mt][1] - mn1)*L2E);
            mr[mt][0] = mn0; mr[mt][1] = mn1;

            float rs0 = 0.f, rs1 = 0.f;
            #pragma unroll
            for (int nt=0;nt<8;nt++){
                S[mt][nt][0] = ex2f((S[mt][nt][0]-mn0)*L2E); rs0 += S[mt][nt][0];
                S[mt][nt][1] = ex2f((S[mt][nt][1]-mn0)*L2E); rs0 += S[mt][nt][1];
                S[mt][nt][2] = ex2f((S[mt][nt][2]-mn1)*L2E); rs1 += S[mt][nt][2];
                S[mt][nt][3] = ex2f((S[mt][nt][3]-mn1)*L2E); rs1 += S[mt][nt][3];
            }
            rs0 += __shfl_xor_sync(0xffffffffu, rs0, 1);
            rs0 += __shfl_xor_sync(0xffffffffu, rs0, 2);
            rs1 += __shfl_xor_sync(0xffffffffu, rs1, 1);
            rs1 += __shfl_xor_sync(0xffffffffu, rs1, 2);
            lr[mt][0] = lr[mt][0]*al0 + rs0;
            lr[mt][1] = lr[mt][1]*al1 + rs1;
            #pragma unroll
            for (int nt=0;nt<8;nt++){
                Oacc[mt][nt][0]*=al0; Oacc[mt][nt][1]*=al0;
                Oacc[mt][nt][2]*=al1; Oacc[mt][nt][3]*=al1;
            }

            const int r = w*32 + mt*16;
            #pragma unroll
            for (int nt=0;nt<8;nt++){
                int c0 = nt*8 + tig*2;
                *(uint2*)&Pb[(r+g  )*AT_PAD + c0] =
                    make_uint2(f2tf(S[mt][nt][0]), f2tf(S[mt][nt][1]));
                *(uint2*)&Pb[(r+g+8)*AT_PAD + c0] =
                    make_uint2(f2tf(S[mt][nt][2]), f2tf(S[mt][nt][3]));
            }
        }
        __syncwarp();

        // ---- O += P V : bv from transposed V tile [d][s] — conflict-free
        #pragma unroll
        for (int ks=0; ks<8; ks++){
            const int kb = ks*8;
            uint32_t pa[2][4];
            #pragma unroll
            for (int mt=0; mt<2; mt++){
                const int r = w*32 + mt*16;
                pa[mt][0]=Pb[(r+g  )*AT_PAD + kb+tig  ];
                pa[mt][1]=Pb[(r+g+8)*AT_PAD + kb+tig  ];
                pa[mt][2]=Pb[(r+g  )*AT_PAD + kb+tig+4];
                pa[mt][3]=Pb[(r+g+8)*AT_PAD + kb+tig+4];
            }
            #pragma unroll
            for (int nt=0; nt<8; nt++){
                uint32_t bv[2];
                bv[0]=vw[(nt*8+g)*AT_PAD + kb+tig  ];
                bv[1]=vw[(nt*8+g)*AT_PAD + kb+tig+4];
                mma8(Oacc[0][nt], pa[0], bv);
                mma8(Oacc[1][nt], pa[1], bv);
            }
        }
    }

    // ---- Epilogue: out[b, s, h*64+d] = O / l
    #pragma unroll
    for (int mt=0; mt<2; mt++){
        float inv0 = 1.f / lr[mt][0], inv1 = 1.f / lr[mt][1];
        int s0 = q0 + w*32 + mt*16 + g;
        #pragma unroll
        for (int nt=0;nt<8;nt++){
            int d = nt*8 + tig*2;
            float2 v0; v0.x = Oacc[mt][nt][0]*inv0; v0.y = Oacc[mt][nt][1]*inv0;
            *(float2*)(out + ((size_t)b*SS + s0  )*DDIM + h*DH + d) = v0;
            float2 v1; v1.x = Oacc[mt][nt][2]*inv1; v1.y = Oacc[mt][nt][3]*inv1;
            *(float2*)(out + ((size_t)b*SS + s0+8)*DDIM + h*DH + d) = v1;
        }
    }
}

extern "C" void kernel_launch(void* const* d_in, const int* in_sizes, int n_in,
                              void* d_out, int out_size){
    const float* q  = (const float*)d_in[0];
    const float* k  = (const float*)d_in[1];
    const float* v  = (const float*)d_in[2];
    const float* Wq = (const float*)d_in[3];
    const float* Wk = (const float*)d_in[4];
    const float* Wv = (const float*)d_in[5];

    dim3 pg(DDIM/128, MM/128, 3);  // (8, 64, 3) — fused Q/K/V projections
    proj_kernel<<<pg, 256>>>(q, k, v, Wq, Wk, Wv);

    cudaFuncSetAttribute(attn_kernel,
                         cudaFuncAttributeMaxDynamicSharedMemorySize,
                         AT_SMEM_BYTES);
    dim3 ag(SS/128, HH, BB);       // (16, 16, 4)
    attn_kernel<<<ag, 128, AT_SMEM_BYTES>>>((float*)d_out);
}